// round 14
// baseline (speedup 1.0000x reference)
#include <cuda_runtime.h>
#include <cuda_fp16.h>
#include <cstdint>

#define NMAX 100000
#define DIM 128
#define NREL 8
#define KTOT 1152     // 9 * 128
#define AS2 72        // padded smem row stride (halfs) for BK=64 chunks

// Scratch (static device globals; runtime allocation is forbidden)
__device__ __half g_Az[(size_t)NMAX * KTOT];          // [N][9][128]: x | Z_1..Z_8 (fp16)
__device__ __half g_Af[(size_t)NMAX * DIM];           // fp16 activations (gather source)
__device__ __half g_Wf[2 * 9 * DIM * DIM];            // fp16 transposed [bn][n][k] weights
// CSR sort structures (shared by both layers)
__device__ int g_cnt[NMAX * NREL];
__device__ int g_off[NMAX * NREL + 1];
__device__ int g_cursor[NMAX * NREL];
__device__ int g_bsum[1024];
__device__ int g_esrc[640000];

// ---------------------------------------------------------------------------
// fp16 conversions
// ---------------------------------------------------------------------------
// x fp32 -> g_Af AND g_Az chunk 0
__global__ void convert_half_kernel(const float* __restrict__ src, int nelem4) {
    int i = blockIdx.x * blockDim.x + threadIdx.x;
    if (i >= nelem4) return;
    float4 v = ((const float4*)src)[i];
    __half2 h0 = __floats2half2_rn(v.x, v.y);
    __half2 h1 = __floats2half2_rn(v.z, v.w);
    uint2 packed = make_uint2(*reinterpret_cast<unsigned*>(&h0),
                              *reinterpret_cast<unsigned*>(&h1));
    ((uint2*)g_Af)[i] = packed;
    int row = i >> 5;
    ((uint2*)g_Az)[row * 288 + (i & 31)] = packed;   // 288 = 1152/4
}

// weights [k][n] fp32 -> transposed [bn][n][k] fp16
__global__ void wconvert_kernel(const float* __restrict__ root,
                                const float* __restrict__ rel,
                                __half* __restrict__ wf) {
    int i = blockIdx.x * blockDim.x + threadIdx.x;
    if (i >= 9 * DIM * DIM) return;
    int bn = i >> 14;
    int t  = i & 16383;
    int n  = t >> 7;
    int k  = t & 127;
    float w = bn ? rel[(size_t)(bn - 1) * DIM * DIM + k * DIM + n] : root[k * DIM + n];
    wf[i] = __float2half_rn(w);
}

// ---------------------------------------------------------------------------
// CSR build: histogram -> 2-level exclusive scan -> counting sort of src ids
// ---------------------------------------------------------------------------
__global__ void zero_cnt_kernel(int n8v4) {
    int i = blockIdx.x * blockDim.x + threadIdx.x;
    if (i < n8v4) ((int4*)g_cnt)[i] = make_int4(0, 0, 0, 0);
}

__global__ void hist_kernel(const int* __restrict__ ei,
                            const int* __restrict__ et, int e) {
    int i = blockIdx.x * blockDim.x + threadIdx.x;
    if (i >= e) return;
    atomicAdd(&g_cnt[ei[e + i] * NREL + et[i]], 1);
}

__global__ void scan1_kernel(int n8) {
    __shared__ int sm[256];
    int t = threadIdx.x;
    int base = blockIdx.x * 1024 + t * 4;
    int v0 = 0, v1 = 0, v2 = 0, v3 = 0;
    if (base + 0 < n8) v0 = g_cnt[base + 0];
    if (base + 1 < n8) v1 = g_cnt[base + 1];
    if (base + 2 < n8) v2 = g_cnt[base + 2];
    if (base + 3 < n8) v3 = g_cnt[base + 3];
    int tsum = v0 + v1 + v2 + v3;
    sm[t] = tsum;
    __syncthreads();
#pragma unroll
    for (int d = 1; d < 256; d <<= 1) {
        int x = (t >= d) ? sm[t - d] : 0;
        __syncthreads();
        sm[t] += x;
        __syncthreads();
    }
    int run = sm[t] - tsum;
    if (base + 0 < n8) { g_off[base + 0] = run; run += v0; }
    if (base + 1 < n8) { g_off[base + 1] = run; run += v1; }
    if (base + 2 < n8) { g_off[base + 2] = run; run += v2; }
    if (base + 3 < n8) { g_off[base + 3] = run; }
    if (t == 255) g_bsum[blockIdx.x] = sm[255];
}

__global__ void scan2_kernel(int nb) {
    __shared__ int sm[1024];
    int t = threadIdx.x;
    int v = (t < nb) ? g_bsum[t] : 0;
    sm[t] = v;
    __syncthreads();
#pragma unroll
    for (int d = 1; d < 1024; d <<= 1) {
        int x = (t >= d) ? sm[t - d] : 0;
        __syncthreads();
        sm[t] += x;
        __syncthreads();
    }
    if (t < nb) g_bsum[t] = sm[t] - v;
}

__global__ void scan3_kernel(int n8, int e) {
    int i = blockIdx.x * blockDim.x + threadIdx.x;
    if (i < n8) {
        int v = g_off[i] + g_bsum[i >> 10];
        g_off[i] = v;
        g_cursor[i] = v;
    }
    if (i == 0) g_off[n8] = e;
}

__global__ void sort_edges_kernel(const int* __restrict__ ei,
                                  const int* __restrict__ et, int e) {
    int i = blockIdx.x * blockDim.x + threadIdx.x;
    if (i >= e) return;
    int bin = ei[e + i] * NREL + et[i];
    int pos = atomicAdd(&g_cursor[bin], 1);
    g_esrc[pos] = ei[i];
}

// ---------------------------------------------------------------------------
// Aggregate-first: Z[dst][r] = mean_{edges in bin(dst,r)} g_Af[src]  (fp16)
// One warp per dst. Gathers hit the L2-resident 25.6MB g_Af.
// ---------------------------------------------------------------------------
__global__ __launch_bounds__(256) void aggz_kernel(int n)
{
    int gw   = (blockIdx.x * 256 + threadIdx.x) >> 5;
    int lane = threadIdx.x & 31;
    if (gw >= n) return;
    const int dst  = gw;
    const int half = lane >> 4;
    const int hl   = lane & 15;

    int ov = 0;
    if (lane < 9) ov = g_off[dst * NREL + lane];

#pragma unroll
    for (int r = 0; r < NREL; r++) {
        int s0 = __shfl_sync(0xffffffffu, ov, r);
        int s1 = __shfl_sync(0xffffffffu, ov, r + 1);
        int c  = s1 - s0;
        float acc[8];
#pragma unroll
        for (int j = 0; j < 8; j++) acc[j] = 0.0f;
        for (int i = s0 + half; i < s1; i += 2) {
            int src = g_esrc[i];
            const uint4 v = *(const uint4*)(g_Af + ((size_t)src << 7) + hl * 8);
            const __half2* h2 = reinterpret_cast<const __half2*>(&v);
#pragma unroll
            for (int j = 0; j < 4; j++) {
                float2 f = __half22float2(h2[j]);
                acc[2 * j]     += f.x;
                acc[2 * j + 1] += f.y;
            }
        }
#pragma unroll
        for (int j = 0; j < 8; j++)
            acc[j] += __shfl_xor_sync(0xffffffffu, acc[j], 16);
        if (half == 0) {
            float inv = (c > 0) ? 1.0f / (float)c : 0.0f;
            uint4 u;
            __half2 h;
            h = __floats2half2_rn(acc[0] * inv, acc[1] * inv);
            u.x = *reinterpret_cast<unsigned*>(&h);
            h = __floats2half2_rn(acc[2] * inv, acc[3] * inv);
            u.y = *reinterpret_cast<unsigned*>(&h);
            h = __floats2half2_rn(acc[4] * inv, acc[5] * inv);
            u.z = *reinterpret_cast<unsigned*>(&h);
            h = __floats2half2_rn(acc[6] * inv, acc[7] * inv);
            u.w = *reinterpret_cast<unsigned*>(&h);
            *(uint4*)(g_Az + (size_t)dst * KTOT + (r + 1) * DIM + hl * 8) = u;
        }
    }
}

// ---------------------------------------------------------------------------
// Pipelined K=1152 GEMM, 64x64 warp tiles (mma m16n8k16 fp16, fp32 accum):
//   out[128-tile] = g_Az[tile] @ Wstack + bias, then relu.
//   BK=64, 2-stage cp.async double buffer. 128 thr = 4 warps (2 wm x 2 wn),
//   warp tile 64x64 -> 8 LDSM.x4 per 32 MMA per ks (was 6 per 16).
//   mode 0: fp16 -> g_Af + g_Az chunk0. mode 1: fp32 out.
// ---------------------------------------------------------------------------
#define MMA16816(d, a, b)                                                  \
    asm volatile(                                                          \
        "mma.sync.aligned.m16n8k16.row.col.f32.f16.f16.f32 "               \
        "{%0,%1,%2,%3},{%4,%5,%6,%7},{%8,%9},{%0,%1,%2,%3};"               \
        : "+f"(d[0]), "+f"(d[1]), "+f"(d[2]), "+f"(d[3])                   \
        : "r"(a[0]), "r"(a[1]), "r"(a[2]), "r"(a[3]), "r"(b[0]), "r"(b[1]))

#define LDSM4(R, ADDR)                                                     \
    asm volatile("ldmatrix.sync.aligned.m8n8.x4.shared.b16 "               \
                 "{%0,%1,%2,%3}, [%4];"                                    \
                 : "=r"(R[0]), "=r"(R[1]), "=r"(R[2]), "=r"(R[3])          \
                 : "r"(ADDR))

#define CP_ASYNC16(dst, src)                                               \
    asm volatile("cp.async.ca.shared.global [%0], [%1], 16;"               \
                 :: "r"(dst), "l"(src) : "memory")
#define CP_COMMIT()  asm volatile("cp.async.commit_group;" ::: "memory")
#define CP_WAIT(N)   asm volatile("cp.async.wait_group %0;" :: "n"(N) : "memory")

__global__ __launch_bounds__(128) void gemm_k_kernel(
    const __half* __restrict__ wf,   // layer base [9][128][128] (n,k)
    const float* __restrict__ bias,
    float* __restrict__ out32, int nrows, int mode)
{
    extern __shared__ __half smem[];
    const int row0 = blockIdx.x * 128;
    const int tid  = threadIdx.x;
    const int lane = tid & 31;
    const int warp = tid >> 5;
    const int wm   = warp & 1;    // M offset 64*wm
    const int wn   = warp >> 1;   // N offset 64*wn
    const int grp  = lane >> 2;
    const int tg   = lane & 3;

    const unsigned sBase = (unsigned)__cvta_generic_to_shared(smem);
    const unsigned BUF = 128 * AS2 * 2;          // 18432 B
    const unsigned sA0 = sBase, sB0 = sBase + 2 * BUF;

    const unsigned aoff = (unsigned)(((wm * 64 + (lane & 15)) * AS2 +
                                      ((lane >> 4) << 3)) * 2);
    const unsigned boff = (unsigned)(((wn * 64 + ((lane >> 4) << 3) + (lane & 7)) * AS2 +
                                      (((lane >> 3) & 1) << 3)) * 2);

    auto stage = [&](int kc) {
        const unsigned abuf = sA0 + (unsigned)(kc & 1) * BUF;
        const unsigned bbuf = sB0 + (unsigned)(kc & 1) * BUF;
        const int bn   = kc >> 1;
        const int koff = (kc & 1) * 64;
        const __half* Bsrc = wf + (size_t)bn * DIM * DIM + koff;
#pragma unroll
        for (int it = 0; it < 8; it++) {
            int id = tid + it * 128;
            int r  = id >> 3;       // 0..127
            int c  = id & 7;        // 16B chunk within 128B
            int gr = row0 + r;
            unsigned ad = abuf + (unsigned)((r * AS2 + c * 8) * 2);
            if (gr < nrows) {
                CP_ASYNC16(ad, g_Az + (size_t)gr * KTOT + kc * 64 + c * 8);
            } else {
                asm volatile("st.shared.v4.b32 [%0], {%1,%1,%1,%1};"
                             :: "r"(ad), "r"(0u) : "memory");
            }
            CP_ASYNC16(bbuf + (unsigned)((r * AS2 + c * 8) * 2),
                       Bsrc + (size_t)r * DIM + c * 8);
        }
        CP_COMMIT();
    };

    float acc[4][8][4];
#pragma unroll
    for (int mi = 0; mi < 4; mi++)
#pragma unroll
        for (int ni = 0; ni < 8; ni++)
#pragma unroll
            for (int q = 0; q < 4; q++) acc[mi][ni][q] = 0.0f;

    stage(0);
    for (int kc = 0; kc < 18; kc++) {
        if (kc < 17) {
            stage(kc + 1);
            CP_WAIT(1);
        } else {
            CP_WAIT(0);
        }
        __syncthreads();

        const unsigned abuf = sA0 + (unsigned)(kc & 1) * BUF;
        const unsigned bbuf = sB0 + (unsigned)(kc & 1) * BUF;
#pragma unroll
        for (int ks = 0; ks < 4; ks++) {
            const unsigned kb = ks * 32;
            unsigned a[4][4];
#pragma unroll
            for (int mi = 0; mi < 4; mi++)
                LDSM4(a[mi], abuf + aoff + mi * (16 * AS2 * 2) + kb);
            // interleave B chunks to keep only 4 B regs live
#pragma unroll
            for (int p = 0; p < 4; p++) {
                unsigned t[4];
                LDSM4(t, bbuf + boff + p * (16 * AS2 * 2) + kb);
#pragma unroll
                for (int mi = 0; mi < 4; mi++) {
                    MMA16816(acc[mi][2 * p],     a[mi], (t + 0));
                    MMA16816(acc[mi][2 * p + 1], a[mi], (t + 2));
                }
            }
        }
        __syncthreads();   // all warps done with this buffer before restage
    }

    // ---- epilogue: relu(acc + bias) ----
#pragma unroll
    for (int mi = 0; mi < 4; mi++) {
        int r0 = row0 + wm * 64 + mi * 16 + grp;
#pragma unroll
        for (int ni = 0; ni < 8; ni++) {
            int col = wn * 64 + ni * 8 + 2 * tg;
            float b0 = bias[col], b1 = bias[col + 1];
            float v00 = fmaxf(acc[mi][ni][0] + b0, 0.f);
            float v01 = fmaxf(acc[mi][ni][1] + b1, 0.f);
            float v10 = fmaxf(acc[mi][ni][2] + b0, 0.f);
            float v11 = fmaxf(acc[mi][ni][3] + b1, 0.f);
            if (mode == 0) {
                if (r0 < nrows) {
                    __half2 h = __floats2half2_rn(v00, v01);
                    unsigned u = *reinterpret_cast<unsigned*>(&h);
                    *(unsigned*)(g_Af + ((size_t)r0 << 7) + col) = u;
                    *(unsigned*)(g_Az + (size_t)r0 * KTOT + col) = u;
                }
                if (r0 + 8 < nrows) {
                    __half2 h = __floats2half2_rn(v10, v11);
                    unsigned u = *reinterpret_cast<unsigned*>(&h);
                    *(unsigned*)(g_Af + ((size_t)(r0 + 8) << 7) + col) = u;
                    *(unsigned*)(g_Az + (size_t)(r0 + 8) * KTOT + col) = u;
                }
            } else {
                if (r0 < nrows)
                    *(float2*)&out32[(size_t)r0 * DIM + col] = make_float2(v00, v01);
                if (r0 + 8 < nrows)
                    *(float2*)&out32[(size_t)(r0 + 8) * DIM + col] = make_float2(v10, v11);
            }
        }
    }
}

// ---------------------------------------------------------------------------
// Launch
// ---------------------------------------------------------------------------
extern "C" void kernel_launch(void* const* d_in, const int* in_sizes, int n_in,
                              void* d_out, int out_size)
{
    const float* x   = (const float*)d_in[0];
    const int*   ei  = (const int*)d_in[1];  // [2,E] int32
    const int*   et  = (const int*)d_in[2];  // [E]   int32
    const float* rw1 = (const float*)d_in[3];
    const float* ro1 = (const float*)d_in[4];
    const float* b1  = (const float*)d_in[5];
    const float* rw2 = (const float*)d_in[6];
    const float* ro2 = (const float*)d_in[7];
    const float* b2  = (const float*)d_in[8];
    float* out = (float*)d_out;

    const int n = in_sizes[0] / DIM;
    const int e = in_sizes[2];

    __half* wf;
    cudaGetSymbolAddress((void**)&wf, g_Wf);

    const int smem_bytes = 4 * 128 * AS2 * 2;   // 73728
    static bool attr_done = false;
    if (!attr_done) {
        cudaFuncSetAttribute(gemm_k_kernel,
                             cudaFuncAttributeMaxDynamicSharedMemorySize, smem_bytes);
        attr_done = true;
    }

    const int n8 = n * NREL;
    const int nscan = (n8 + 1023) / 1024;
    const int mtiles = (n + 127) / 128;
    const int nw = 9 * DIM * DIM;

    // conversions
    wconvert_kernel<<<(nw + 255) / 256, 256>>>(ro1, rw1, wf);
    wconvert_kernel<<<(nw + 255) / 256, 256>>>(ro2, rw2, wf + nw);
    convert_half_kernel<<<(n * 32 + 255) / 256, 256>>>(x, n * 32);

    // CSR build (shared by both layers)
    zero_cnt_kernel<<<(n8 / 4 + 255) / 256, 256>>>(n8 / 4);
    hist_kernel<<<(e + 255) / 256, 256>>>(ei, et, e);
    scan1_kernel<<<nscan, 256>>>(n8);
    scan2_kernel<<<1, 1024>>>(nscan);
    scan3_kernel<<<(n8 + 255) / 256, 256>>>(n8, e);
    sort_edges_kernel<<<(e + 255) / 256, 256>>>(ei, et, e);

    // layer 1: aggregate x into Z, then K=1152 GEMM -> fp16 activations
    aggz_kernel<<<(n * 32 + 255) / 256, 256>>>(n);
    gemm_k_kernel<<<mtiles, 128, smem_bytes>>>(wf, b1, nullptr, n, 0);

    // layer 2: aggregate h into Z, then GEMM -> fp32 out (relu fused)
    aggz_kernel<<<(n * 32 + 255) / 256, 256>>>(n);
    gemm_k_kernel<<<mtiles, 128, smem_bytes>>>(wf + nw, b2, out, n, 1);
}

// round 16
// speedup vs baseline: 1.0734x; 1.0734x over previous
#include <cuda_runtime.h>
#include <cuda_fp16.h>
#include <cstdint>

#define NMAX 100000
#define DIM 128
#define NREL 8
#define KTOT 1152     // 9 * 128
#define AS2 72        // padded smem row stride (halfs) for BK=64 chunks

// Scratch (static device globals; runtime allocation is forbidden)
__device__ __half g_Az[(size_t)NMAX * KTOT];          // [N][9][128]: x | Z_1..Z_8 (fp16)
__device__ __half g_Af[(size_t)NMAX * DIM];           // fp16 activations (gather source)
__device__ __half g_Wf[2 * 9 * DIM * DIM];            // fp16 transposed [bn][n][k] weights
// CSR sort structures (shared by both layers)
__device__ int g_cnt[NMAX * NREL];
__device__ int g_off[NMAX * NREL + 1];
__device__ int g_cursor[NMAX * NREL];
__device__ int g_bsum[1024];
__device__ int g_esrc[640000];

// ---------------------------------------------------------------------------
// fp16 conversions
// ---------------------------------------------------------------------------
// x fp32 -> g_Af AND g_Az chunk 0
__global__ void convert_half_kernel(const float* __restrict__ src, int nelem4) {
    int i = blockIdx.x * blockDim.x + threadIdx.x;
    if (i >= nelem4) return;
    float4 v = ((const float4*)src)[i];
    __half2 h0 = __floats2half2_rn(v.x, v.y);
    __half2 h1 = __floats2half2_rn(v.z, v.w);
    uint2 packed = make_uint2(*reinterpret_cast<unsigned*>(&h0),
                              *reinterpret_cast<unsigned*>(&h1));
    ((uint2*)g_Af)[i] = packed;
    int row = i >> 5;
    ((uint2*)g_Az)[row * 288 + (i & 31)] = packed;   // 288 = 1152/4
}

// weights [k][n] fp32 -> transposed [bn][n][k] fp16
__global__ void wconvert_kernel(const float* __restrict__ root,
                                const float* __restrict__ rel,
                                __half* __restrict__ wf) {
    int i = blockIdx.x * blockDim.x + threadIdx.x;
    if (i >= 9 * DIM * DIM) return;
    int bn = i >> 14;
    int t  = i & 16383;
    int n  = t >> 7;
    int k  = t & 127;
    float w = bn ? rel[(size_t)(bn - 1) * DIM * DIM + k * DIM + n] : root[k * DIM + n];
    wf[i] = __float2half_rn(w);
}

// ---------------------------------------------------------------------------
// CSR build: histogram -> 2-level exclusive scan -> counting sort of src ids
// ---------------------------------------------------------------------------
__global__ void zero_cnt_kernel(int n8v4) {
    int i = blockIdx.x * blockDim.x + threadIdx.x;
    if (i < n8v4) ((int4*)g_cnt)[i] = make_int4(0, 0, 0, 0);
}

__global__ void hist_kernel(const int* __restrict__ ei,
                            const int* __restrict__ et, int e) {
    int i = blockIdx.x * blockDim.x + threadIdx.x;
    if (i >= e) return;
    atomicAdd(&g_cnt[ei[e + i] * NREL + et[i]], 1);
}

__global__ void scan1_kernel(int n8) {
    __shared__ int sm[256];
    int t = threadIdx.x;
    int base = blockIdx.x * 1024 + t * 4;
    int v0 = 0, v1 = 0, v2 = 0, v3 = 0;
    if (base + 0 < n8) v0 = g_cnt[base + 0];
    if (base + 1 < n8) v1 = g_cnt[base + 1];
    if (base + 2 < n8) v2 = g_cnt[base + 2];
    if (base + 3 < n8) v3 = g_cnt[base + 3];
    int tsum = v0 + v1 + v2 + v3;
    sm[t] = tsum;
    __syncthreads();
#pragma unroll
    for (int d = 1; d < 256; d <<= 1) {
        int x = (t >= d) ? sm[t - d] : 0;
        __syncthreads();
        sm[t] += x;
        __syncthreads();
    }
    int run = sm[t] - tsum;
    if (base + 0 < n8) { g_off[base + 0] = run; run += v0; }
    if (base + 1 < n8) { g_off[base + 1] = run; run += v1; }
    if (base + 2 < n8) { g_off[base + 2] = run; run += v2; }
    if (base + 3 < n8) { g_off[base + 3] = run; }
    if (t == 255) g_bsum[blockIdx.x] = sm[255];
}

__global__ void scan2_kernel(int nb) {
    __shared__ int sm[1024];
    int t = threadIdx.x;
    int v = (t < nb) ? g_bsum[t] : 0;
    sm[t] = v;
    __syncthreads();
#pragma unroll
    for (int d = 1; d < 1024; d <<= 1) {
        int x = (t >= d) ? sm[t - d] : 0;
        __syncthreads();
        sm[t] += x;
        __syncthreads();
    }
    if (t < nb) g_bsum[t] = sm[t] - v;
}

__global__ void scan3_kernel(int n8, int e) {
    int i = blockIdx.x * blockDim.x + threadIdx.x;
    if (i < n8) {
        int v = g_off[i] + g_bsum[i >> 10];
        g_off[i] = v;
        g_cursor[i] = v;
    }
    if (i == 0) g_off[n8] = e;
}

__global__ void sort_edges_kernel(const int* __restrict__ ei,
                                  const int* __restrict__ et, int e) {
    int i = blockIdx.x * blockDim.x + threadIdx.x;
    if (i >= e) return;
    int bin = ei[e + i] * NREL + et[i];
    int pos = atomicAdd(&g_cursor[bin], 1);
    g_esrc[pos] = ei[i];
}

// ---------------------------------------------------------------------------
// Aggregate-first: Z[dst][r] = mean_{edges in bin(dst,r)} g_Af[src]  (fp16)
// One warp per dst. Fast paths: c==0 store zeros; c==1 exact row copy.
// ---------------------------------------------------------------------------
__global__ __launch_bounds__(256) void aggz_kernel(int n)
{
    int gw   = (blockIdx.x * 256 + threadIdx.x) >> 5;
    int lane = threadIdx.x & 31;
    if (gw >= n) return;
    const int dst  = gw;
    const int half = lane >> 4;
    const int hl   = lane & 15;

    int ov = 0;
    if (lane < 9) ov = g_off[dst * NREL + lane];

#pragma unroll
    for (int r = 0; r < NREL; r++) {
        int s0 = __shfl_sync(0xffffffffu, ov, r);
        int s1 = __shfl_sync(0xffffffffu, ov, r + 1);
        int c  = s1 - s0;
        __half* zdst = g_Az + (size_t)dst * KTOT + (r + 1) * DIM;
        if (c == 0) {
            if (half == 0)
                *(uint4*)(zdst + hl * 8) = make_uint4(0, 0, 0, 0);
            continue;
        }
        if (c == 1) {   // mean of one element == element: exact fp16 copy
            if (half == 0) {
                int src = g_esrc[s0];
                *(uint4*)(zdst + hl * 8) =
                    *(const uint4*)(g_Af + ((size_t)src << 7) + hl * 8);
            }
            continue;
        }
        float acc[8];
#pragma unroll
        for (int j = 0; j < 8; j++) acc[j] = 0.0f;
        for (int i = s0 + half; i < s1; i += 2) {
            int src = g_esrc[i];
            const uint4 v = *(const uint4*)(g_Af + ((size_t)src << 7) + hl * 8);
            const __half2* h2 = reinterpret_cast<const __half2*>(&v);
#pragma unroll
            for (int j = 0; j < 4; j++) {
                float2 f = __half22float2(h2[j]);
                acc[2 * j]     += f.x;
                acc[2 * j + 1] += f.y;
            }
        }
#pragma unroll
        for (int j = 0; j < 8; j++)
            acc[j] += __shfl_xor_sync(0xffffffffu, acc[j], 16);
        if (half == 0) {
            float inv = 1.0f / (float)c;
            uint4 u;
            __half2 h;
            h = __floats2half2_rn(acc[0] * inv, acc[1] * inv);
            u.x = *reinterpret_cast<unsigned*>(&h);
            h = __floats2half2_rn(acc[2] * inv, acc[3] * inv);
            u.y = *reinterpret_cast<unsigned*>(&h);
            h = __floats2half2_rn(acc[4] * inv, acc[5] * inv);
            u.z = *reinterpret_cast<unsigned*>(&h);
            h = __floats2half2_rn(acc[6] * inv, acc[7] * inv);
            u.w = *reinterpret_cast<unsigned*>(&h);
            *(uint4*)(zdst + hl * 8) = u;
        }
    }
}

// ---------------------------------------------------------------------------
// Pipelined K=1152 GEMM (3-stage cp.async, 1 sync/kc, CORRECT tail wait):
//   out[128-tile] = g_Az[tile] @ Wstack + bias, then relu.
//   BK=64, 3-stage. 256 thr = 8 warps (4 wm x 2 wn), warp tile 32x64.
//   mode 0: fp16 -> g_Af + g_Az chunk0. mode 1: fp32 out.
// ---------------------------------------------------------------------------
#define MMA16816(d, a, b)                                                  \
    asm volatile(                                                          \
        "mma.sync.aligned.m16n8k16.row.col.f32.f16.f16.f32 "               \
        "{%0,%1,%2,%3},{%4,%5,%6,%7},{%8,%9},{%0,%1,%2,%3};"               \
        : "+f"(d[0]), "+f"(d[1]), "+f"(d[2]), "+f"(d[3])                   \
        : "r"(a[0]), "r"(a[1]), "r"(a[2]), "r"(a[3]), "r"(b[0]), "r"(b[1]))

#define LDSM4(R, ADDR)                                                     \
    asm volatile("ldmatrix.sync.aligned.m8n8.x4.shared.b16 "               \
                 "{%0,%1,%2,%3}, [%4];"                                    \
                 : "=r"(R[0]), "=r"(R[1]), "=r"(R[2]), "=r"(R[3])          \
                 : "r"(ADDR))

#define CP_ASYNC16(dst, src)                                               \
    asm volatile("cp.async.ca.shared.global [%0], [%1], 16;"               \
                 :: "r"(dst), "l"(src) : "memory")
#define CP_COMMIT()  asm volatile("cp.async.commit_group;" ::: "memory")
#define CP_WAIT(N)   asm volatile("cp.async.wait_group %0;" :: "n"(N) : "memory")

__global__ __launch_bounds__(256) void gemm_k_kernel(
    const __half* __restrict__ wf,   // layer base [9][128][128] (n,k)
    const float* __restrict__ bias,
    float* __restrict__ out32, int nrows, int mode)
{
    extern __shared__ __half smem[];
    const int row0 = blockIdx.x * 128;
    const int tid  = threadIdx.x;
    const int lane = tid & 31;
    const int warp = tid >> 5;
    const int wm   = warp & 3;
    const int wn   = warp >> 2;
    const int grp  = lane >> 2;
    const int tg   = lane & 3;

    const unsigned sBase = (unsigned)__cvta_generic_to_shared(smem);
    const unsigned BUF = 128 * AS2 * 2;          // 18432 B
    const unsigned sA0 = sBase, sB0 = sBase + 3 * BUF;

    const unsigned aoff = (unsigned)(((wm * 32 + (lane & 15)) * AS2 +
                                      ((lane >> 4) << 3)) * 2);
    const unsigned boff = (unsigned)(((wn * 64 + ((lane >> 4) << 3) + (lane & 7)) * AS2 +
                                      (((lane >> 3) & 1) << 3)) * 2);

    auto stage = [&](int kc) {
        const unsigned sel = (unsigned)(kc % 3) * BUF;
        const unsigned abuf = sA0 + sel;
        const unsigned bbuf = sB0 + sel;
        const int bn   = kc >> 1;
        const int koff = (kc & 1) * 64;
        const __half* Bsrc = wf + (size_t)bn * DIM * DIM + koff;
#pragma unroll
        for (int it = 0; it < 4; it++) {
            int id = tid + it * 256;
            int r  = id >> 3;       // 0..127
            int c  = id & 7;        // 16B chunk within 128B
            int gr = row0 + r;
            unsigned ad = abuf + (unsigned)((r * AS2 + c * 8) * 2);
            if (gr < nrows) {
                CP_ASYNC16(ad, g_Az + (size_t)gr * KTOT + kc * 64 + c * 8);
            } else {
                asm volatile("st.shared.v4.b32 [%0], {%1,%1,%1,%1};"
                             :: "r"(ad), "r"(0u) : "memory");
            }
            CP_ASYNC16(bbuf + (unsigned)((r * AS2 + c * 8) * 2),
                       Bsrc + (size_t)r * DIM + c * 8);
        }
        CP_COMMIT();
    };

    float acc[2][8][4];
#pragma unroll
    for (int mi = 0; mi < 2; mi++)
#pragma unroll
        for (int ni = 0; ni < 8; ni++)
#pragma unroll
            for (int q = 0; q < 4; q++) acc[mi][ni][q] = 0.0f;

    stage(0);
    stage(1);
    for (int kc = 0; kc < 18; kc++) {
        // Wait for stage(kc). For kc<17 one newer group (kc+1) may remain in
        // flight; at kc==17 NO newer group exists, so must wait for ALL.
        if (kc < 17) CP_WAIT(1); else CP_WAIT(0);
        __syncthreads();     // also: all warps done reading buf (kc+2)%3 at kc-1

        const unsigned sel = (unsigned)(kc % 3) * BUF;
        const unsigned abuf = sA0 + sel;
        const unsigned bbuf = sB0 + sel;
#pragma unroll
        for (int ks = 0; ks < 4; ks++) {
            const unsigned kb = ks * 32;
            unsigned a[2][4];
#pragma unroll
            for (int mi = 0; mi < 2; mi++)
                LDSM4(a[mi], abuf + aoff + mi * (16 * AS2 * 2) + kb);
            unsigned b[8][2];
#pragma unroll
            for (int p = 0; p < 4; p++) {
                unsigned t[4];
                LDSM4(t, bbuf + boff + p * (16 * AS2 * 2) + kb);
                b[2 * p][0] = t[0]; b[2 * p][1] = t[1];
                b[2 * p + 1][0] = t[2]; b[2 * p + 1][1] = t[3];
            }
#pragma unroll
            for (int ni = 0; ni < 8; ni++)
#pragma unroll
                for (int mi = 0; mi < 2; mi++)
                    MMA16816(acc[mi][ni], a[mi], b[ni]);
        }

        if (kc < 16) stage(kc + 2);   // buf (kc+2)%3 free since sync above
    }

    // ---- epilogue: relu(acc + bias) ----
#pragma unroll
    for (int mi = 0; mi < 2; mi++) {
        int r0 = row0 + wm * 32 + mi * 16 + grp;
#pragma unroll
        for (int ni = 0; ni < 8; ni++) {
            int col = wn * 64 + ni * 8 + 2 * tg;
            float b0 = bias[col], b1 = bias[col + 1];
            float v00 = fmaxf(acc[mi][ni][0] + b0, 0.f);
            float v01 = fmaxf(acc[mi][ni][1] + b1, 0.f);
            float v10 = fmaxf(acc[mi][ni][2] + b0, 0.f);
            float v11 = fmaxf(acc[mi][ni][3] + b1, 0.f);
            if (mode == 0) {
                if (r0 < nrows) {
                    __half2 h = __floats2half2_rn(v00, v01);
                    unsigned u = *reinterpret_cast<unsigned*>(&h);
                    *(unsigned*)(g_Af + ((size_t)r0 << 7) + col) = u;
                    *(unsigned*)(g_Az + (size_t)r0 * KTOT + col) = u;
                }
                if (r0 + 8 < nrows) {
                    __half2 h = __floats2half2_rn(v10, v11);
                    unsigned u = *reinterpret_cast<unsigned*>(&h);
                    *(unsigned*)(g_Af + ((size_t)(r0 + 8) << 7) + col) = u;
                    *(unsigned*)(g_Az + (size_t)(r0 + 8) * KTOT + col) = u;
                }
            } else {
                if (r0 < nrows)
                    *(float2*)&out32[(size_t)r0 * DIM + col] = make_float2(v00, v01);
                if (r0 + 8 < nrows)
                    *(float2*)&out32[(size_t)(r0 + 8) * DIM + col] = make_float2(v10, v11);
            }
        }
    }
}

// ---------------------------------------------------------------------------
// Launch
// ---------------------------------------------------------------------------
extern "C" void kernel_launch(void* const* d_in, const int* in_sizes, int n_in,
                              void* d_out, int out_size)
{
    const float* x   = (const float*)d_in[0];
    const int*   ei  = (const int*)d_in[1];  // [2,E] int32
    const int*   et  = (const int*)d_in[2];  // [E]   int32
    const float* rw1 = (const float*)d_in[3];
    const float* ro1 = (const float*)d_in[4];
    const float* b1  = (const float*)d_in[5];
    const float* rw2 = (const float*)d_in[6];
    const float* ro2 = (const float*)d_in[7];
    const float* b2  = (const float*)d_in[8];
    float* out = (float*)d_out;

    const int n = in_sizes[0] / DIM;
    const int e = in_sizes[2];

    __half* wf;
    cudaGetSymbolAddress((void**)&wf, g_Wf);

    const int smem_bytes = 6 * 128 * AS2 * 2;   // 110592 (3-stage A+B)
    static bool attr_done = false;
    if (!attr_done) {
        cudaFuncSetAttribute(gemm_k_kernel,
                             cudaFuncAttributeMaxDynamicSharedMemorySize, smem_bytes);
        attr_done = true;
    }

    const int n8 = n * NREL;
    const int nscan = (n8 + 1023) / 1024;
    const int mtiles = (n + 127) / 128;
    const int nw = 9 * DIM * DIM;

    // conversions
    wconvert_kernel<<<(nw + 255) / 256, 256>>>(ro1, rw1, wf);
    wconvert_kernel<<<(nw + 255) / 256, 256>>>(ro2, rw2, wf + nw);
    convert_half_kernel<<<(n * 32 + 255) / 256, 256>>>(x, n * 32);

    // CSR build (shared by both layers)
    zero_cnt_kernel<<<(n8 / 4 + 255) / 256, 256>>>(n8 / 4);
    hist_kernel<<<(e + 255) / 256, 256>>>(ei, et, e);
    scan1_kernel<<<nscan, 256>>>(n8);
    scan2_kernel<<<1, 1024>>>(nscan);
    scan3_kernel<<<(n8 + 255) / 256, 256>>>(n8, e);
    sort_edges_kernel<<<(e + 255) / 256, 256>>>(ei, et, e);

    // layer 1: aggregate x into Z, then K=1152 GEMM -> fp16 activations
    aggz_kernel<<<(n * 32 + 255) / 256, 256>>>(n);
    gemm_k_kernel<<<mtiles, 256, smem_bytes>>>(wf, b1, nullptr, n, 0);

    // layer 2: aggregate h into Z, then GEMM -> fp32 out (relu fused)
    aggz_kernel<<<(n * 32 + 255) / 256, 256>>>(n);
    gemm_k_kernel<<<mtiles, 256, smem_bytes>>>(wf + nw, b2, out, n, 1);
}

// round 17
// speedup vs baseline: 1.3062x; 1.2168x over previous
#include <cuda_runtime.h>
#include <cuda_fp16.h>
#include <cstdint>

#define NMAX 100000
#define DIM 128
#define NREL 8
#define KTOT 1152     // 9 * 128
#define AS2 72        // padded smem row stride (halfs) for BK=64 chunks

// Scratch (static device globals; runtime allocation is forbidden)
__device__ __half g_Az[(size_t)NMAX * KTOT];          // [N][9][128]: x | Z_1..Z_8 (fp16)
__device__ __half g_Af[(size_t)NMAX * DIM];           // fp16 activations (gather source)
__device__ __half g_Wf[2 * 9 * DIM * DIM];            // fp16 transposed [bn][n][k] weights
// CSR sort structures (shared by both layers)
__device__ int g_cnt[NMAX * NREL];
__device__ int g_off[NMAX * NREL + 1];
__device__ int g_cursor[NMAX * NREL];
__device__ int g_bsum[1024];
__device__ int g_esrc[640000];

// ---------------------------------------------------------------------------
// fp16 conversions
// ---------------------------------------------------------------------------
// x fp32 -> g_Af AND g_Az chunk 0
__global__ void convert_half_kernel(const float* __restrict__ src, int nelem4) {
    int i = blockIdx.x * blockDim.x + threadIdx.x;
    if (i >= nelem4) return;
    float4 v = ((const float4*)src)[i];
    __half2 h0 = __floats2half2_rn(v.x, v.y);
    __half2 h1 = __floats2half2_rn(v.z, v.w);
    uint2 packed = make_uint2(*reinterpret_cast<unsigned*>(&h0),
                              *reinterpret_cast<unsigned*>(&h1));
    ((uint2*)g_Af)[i] = packed;
    int row = i >> 5;
    ((uint2*)g_Az)[row * 288 + (i & 31)] = packed;   // 288 = 1152/4
}

// weights [k][n] fp32 -> transposed [bn][n][k] fp16
__global__ void wconvert_kernel(const float* __restrict__ root,
                                const float* __restrict__ rel,
                                __half* __restrict__ wf) {
    int i = blockIdx.x * blockDim.x + threadIdx.x;
    if (i >= 9 * DIM * DIM) return;
    int bn = i >> 14;
    int t  = i & 16383;
    int n  = t >> 7;
    int k  = t & 127;
    float w = bn ? rel[(size_t)(bn - 1) * DIM * DIM + k * DIM + n] : root[k * DIM + n];
    wf[i] = __float2half_rn(w);
}

// ---------------------------------------------------------------------------
// CSR build: histogram -> 2-level exclusive scan -> counting sort of src ids
// ---------------------------------------------------------------------------
__global__ void zero_cnt_kernel(int n8v4) {
    int i = blockIdx.x * blockDim.x + threadIdx.x;
    if (i < n8v4) ((int4*)g_cnt)[i] = make_int4(0, 0, 0, 0);
}

__global__ void hist_kernel(const int* __restrict__ ei,
                            const int* __restrict__ et, int e) {
    int i = blockIdx.x * blockDim.x + threadIdx.x;
    if (i >= e) return;
    atomicAdd(&g_cnt[ei[e + i] * NREL + et[i]], 1);
}

__global__ void scan1_kernel(int n8) {
    __shared__ int sm[256];
    int t = threadIdx.x;
    int base = blockIdx.x * 1024 + t * 4;
    int v0 = 0, v1 = 0, v2 = 0, v3 = 0;
    if (base + 0 < n8) v0 = g_cnt[base + 0];
    if (base + 1 < n8) v1 = g_cnt[base + 1];
    if (base + 2 < n8) v2 = g_cnt[base + 2];
    if (base + 3 < n8) v3 = g_cnt[base + 3];
    int tsum = v0 + v1 + v2 + v3;
    sm[t] = tsum;
    __syncthreads();
#pragma unroll
    for (int d = 1; d < 256; d <<= 1) {
        int x = (t >= d) ? sm[t - d] : 0;
        __syncthreads();
        sm[t] += x;
        __syncthreads();
    }
    int run = sm[t] - tsum;
    if (base + 0 < n8) { g_off[base + 0] = run; run += v0; }
    if (base + 1 < n8) { g_off[base + 1] = run; run += v1; }
    if (base + 2 < n8) { g_off[base + 2] = run; run += v2; }
    if (base + 3 < n8) { g_off[base + 3] = run; }
    if (t == 255) g_bsum[blockIdx.x] = sm[255];
}

__global__ void scan2_kernel(int nb) {
    __shared__ int sm[1024];
    int t = threadIdx.x;
    int v = (t < nb) ? g_bsum[t] : 0;
    sm[t] = v;
    __syncthreads();
#pragma unroll
    for (int d = 1; d < 1024; d <<= 1) {
        int x = (t >= d) ? sm[t - d] : 0;
        __syncthreads();
        sm[t] += x;
        __syncthreads();
    }
    if (t < nb) g_bsum[t] = sm[t] - v;
}

__global__ void scan3_kernel(int n8, int e) {
    int i = blockIdx.x * blockDim.x + threadIdx.x;
    if (i < n8) {
        int v = g_off[i] + g_bsum[i >> 10];
        g_off[i] = v;
        g_cursor[i] = v;
    }
    if (i == 0) g_off[n8] = e;
}

__global__ void sort_edges_kernel(const int* __restrict__ ei,
                                  const int* __restrict__ et, int e) {
    int i = blockIdx.x * blockDim.x + threadIdx.x;
    if (i >= e) return;
    int bin = ei[e + i] * NREL + et[i];
    int pos = atomicAdd(&g_cursor[bin], 1);
    g_esrc[pos] = ei[i];
}

// ---------------------------------------------------------------------------
// Aggregate-first: Z[dst][r] = mean_{edges in bin(dst,r)} g_Af[src]  (fp16)
// One warp per dst. Fast paths: c==0 store zeros; c==1 exact row copy.
// ---------------------------------------------------------------------------
__global__ __launch_bounds__(256) void aggz_kernel(int n)
{
    int gw   = (blockIdx.x * 256 + threadIdx.x) >> 5;
    int lane = threadIdx.x & 31;
    if (gw >= n) return;
    const int dst  = gw;
    const int half = lane >> 4;
    const int hl   = lane & 15;

    int ov = 0;
    if (lane < 9) ov = g_off[dst * NREL + lane];

#pragma unroll
    for (int r = 0; r < NREL; r++) {
        int s0 = __shfl_sync(0xffffffffu, ov, r);
        int s1 = __shfl_sync(0xffffffffu, ov, r + 1);
        int c  = s1 - s0;
        __half* zdst = g_Az + (size_t)dst * KTOT + (r + 1) * DIM;
        if (c == 0) {
            if (half == 0)
                *(uint4*)(zdst + hl * 8) = make_uint4(0, 0, 0, 0);
            continue;
        }
        if (c == 1) {   // mean of one element == element: exact fp16 copy
            if (half == 0) {
                int src = g_esrc[s0];
                *(uint4*)(zdst + hl * 8) =
                    *(const uint4*)(g_Af + ((size_t)src << 7) + hl * 8);
            }
            continue;
        }
        float acc[8];
#pragma unroll
        for (int j = 0; j < 8; j++) acc[j] = 0.0f;
        for (int i = s0 + half; i < s1; i += 2) {
            int src = g_esrc[i];
            const uint4 v = *(const uint4*)(g_Af + ((size_t)src << 7) + hl * 8);
            const __half2* h2 = reinterpret_cast<const __half2*>(&v);
#pragma unroll
            for (int j = 0; j < 4; j++) {
                float2 f = __half22float2(h2[j]);
                acc[2 * j]     += f.x;
                acc[2 * j + 1] += f.y;
            }
        }
#pragma unroll
        for (int j = 0; j < 8; j++)
            acc[j] += __shfl_xor_sync(0xffffffffu, acc[j], 16);
        if (half == 0) {
            float inv = 1.0f / (float)c;
            uint4 u;
            __half2 h;
            h = __floats2half2_rn(acc[0] * inv, acc[1] * inv);
            u.x = *reinterpret_cast<unsigned*>(&h);
            h = __floats2half2_rn(acc[2] * inv, acc[3] * inv);
            u.y = *reinterpret_cast<unsigned*>(&h);
            h = __floats2half2_rn(acc[4] * inv, acc[5] * inv);
            u.z = *reinterpret_cast<unsigned*>(&h);
            h = __floats2half2_rn(acc[6] * inv, acc[7] * inv);
            u.w = *reinterpret_cast<unsigned*>(&h);
            *(uint4*)(zdst + hl * 8) = u;
        }
    }
}

// ---------------------------------------------------------------------------
// Pipelined K=1152 GEMM (round-13 exact: BK=64, 2-stage cp.async double
// buffer, 256 thr = 8 warps (4 wm x 2 wn), warp tile 32x64, 2 CTAs/SM):
//   out[128-tile] = g_Az[tile] @ Wstack + bias, then relu.
//   mode 0: fp16 -> g_Af + g_Az chunk0. mode 1: fp32 out.
// ---------------------------------------------------------------------------
#define MMA16816(d, a, b)                                                  \
    asm volatile(                                                          \
        "mma.sync.aligned.m16n8k16.row.col.f32.f16.f16.f32 "               \
        "{%0,%1,%2,%3},{%4,%5,%6,%7},{%8,%9},{%0,%1,%2,%3};"               \
        : "+f"(d[0]), "+f"(d[1]), "+f"(d[2]), "+f"(d[3])                   \
        : "r"(a[0]), "r"(a[1]), "r"(a[2]), "r"(a[3]), "r"(b[0]), "r"(b[1]))

#define LDSM4(R, ADDR)                                                     \
    asm volatile("ldmatrix.sync.aligned.m8n8.x4.shared.b16 "               \
                 "{%0,%1,%2,%3}, [%4];"                                    \
                 : "=r"(R[0]), "=r"(R[1]), "=r"(R[2]), "=r"(R[3])          \
                 : "r"(ADDR))

#define CP_ASYNC16(dst, src)                                               \
    asm volatile("cp.async.ca.shared.global [%0], [%1], 16;"               \
                 :: "r"(dst), "l"(src) : "memory")
#define CP_COMMIT()  asm volatile("cp.async.commit_group;" ::: "memory")
#define CP_WAIT(N)   asm volatile("cp.async.wait_group %0;" :: "n"(N) : "memory")

__global__ __launch_bounds__(256) void gemm_k_kernel(
    const __half* __restrict__ wf,   // layer base [9][128][128] (n,k)
    const float* __restrict__ bias,
    float* __restrict__ out32, int nrows, int mode)
{
    extern __shared__ __half smem[];
    const int row0 = blockIdx.x * 128;
    const int tid  = threadIdx.x;
    const int lane = tid & 31;
    const int warp = tid >> 5;
    const int wm   = warp & 3;
    const int wn   = warp >> 2;
    const int grp  = lane >> 2;
    const int tg   = lane & 3;

    const unsigned sBase = (unsigned)__cvta_generic_to_shared(smem);
    const unsigned BUF = 128 * AS2 * 2;          // 18432 B
    const unsigned sA0 = sBase, sB0 = sBase + 2 * BUF;

    const unsigned aoff = (unsigned)(((wm * 32 + (lane & 15)) * AS2 +
                                      ((lane >> 4) << 3)) * 2);
    const unsigned boff = (unsigned)(((wn * 64 + ((lane >> 4) << 3) + (lane & 7)) * AS2 +
                                      (((lane >> 3) & 1) << 3)) * 2);

    auto stage = [&](int kc) {
        const unsigned abuf = sA0 + (unsigned)(kc & 1) * BUF;
        const unsigned bbuf = sB0 + (unsigned)(kc & 1) * BUF;
        const int bn   = kc >> 1;
        const int koff = (kc & 1) * 64;
        const __half* Bsrc = wf + (size_t)bn * DIM * DIM + koff;
#pragma unroll
        for (int it = 0; it < 4; it++) {
            int id = tid + it * 256;
            int r  = id >> 3;       // 0..127
            int c  = id & 7;        // 16B chunk within 128B
            int gr = row0 + r;
            unsigned ad = abuf + (unsigned)((r * AS2 + c * 8) * 2);
            if (gr < nrows) {
                CP_ASYNC16(ad, g_Az + (size_t)gr * KTOT + kc * 64 + c * 8);
            } else {
                asm volatile("st.shared.v4.b32 [%0], {%1,%1,%1,%1};"
                             :: "r"(ad), "r"(0u) : "memory");
            }
            CP_ASYNC16(bbuf + (unsigned)((r * AS2 + c * 8) * 2),
                       Bsrc + (size_t)r * DIM + c * 8);
        }
        CP_COMMIT();
    };

    float acc[2][8][4];
#pragma unroll
    for (int mi = 0; mi < 2; mi++)
#pragma unroll
        for (int ni = 0; ni < 8; ni++)
#pragma unroll
            for (int q = 0; q < 4; q++) acc[mi][ni][q] = 0.0f;

    stage(0);
    for (int kc = 0; kc < 18; kc++) {
        if (kc < 17) {
            stage(kc + 1);
            CP_WAIT(1);
        } else {
            CP_WAIT(0);
        }
        __syncthreads();

        const unsigned abuf = sA0 + (unsigned)(kc & 1) * BUF;
        const unsigned bbuf = sB0 + (unsigned)(kc & 1) * BUF;
#pragma unroll
        for (int ks = 0; ks < 4; ks++) {
            const unsigned kb = ks * 32;
            unsigned a[2][4];
#pragma unroll
            for (int mi = 0; mi < 2; mi++)
                LDSM4(a[mi], abuf + aoff + mi * (16 * AS2 * 2) + kb);
            unsigned b[8][2];
#pragma unroll
            for (int p = 0; p < 4; p++) {
                unsigned t[4];
                LDSM4(t, bbuf + boff + p * (16 * AS2 * 2) + kb);
                b[2 * p][0] = t[0]; b[2 * p][1] = t[1];
                b[2 * p + 1][0] = t[2]; b[2 * p + 1][1] = t[3];
            }
#pragma unroll
            for (int ni = 0; ni < 8; ni++)
#pragma unroll
                for (int mi = 0; mi < 2; mi++)
                    MMA16816(acc[mi][ni], a[mi], b[ni]);
        }
        __syncthreads();   // all warps done with this buffer before restage
    }

    // ---- epilogue: relu(acc + bias) ----
#pragma unroll
    for (int mi = 0; mi < 2; mi++) {
        int r0 = row0 + wm * 32 + mi * 16 + grp;
#pragma unroll
        for (int ni = 0; ni < 8; ni++) {
            int col = wn * 64 + ni * 8 + 2 * tg;
            float b0 = bias[col], b1 = bias[col + 1];
            float v00 = fmaxf(acc[mi][ni][0] + b0, 0.f);
            float v01 = fmaxf(acc[mi][ni][1] + b1, 0.f);
            float v10 = fmaxf(acc[mi][ni][2] + b0, 0.f);
            float v11 = fmaxf(acc[mi][ni][3] + b1, 0.f);
            if (mode == 0) {
                if (r0 < nrows) {
                    __half2 h = __floats2half2_rn(v00, v01);
                    unsigned u = *reinterpret_cast<unsigned*>(&h);
                    *(unsigned*)(g_Af + ((size_t)r0 << 7) + col) = u;
                    *(unsigned*)(g_Az + (size_t)r0 * KTOT + col) = u;
                }
                if (r0 + 8 < nrows) {
                    __half2 h = __floats2half2_rn(v10, v11);
                    unsigned u = *reinterpret_cast<unsigned*>(&h);
                    *(unsigned*)(g_Af + ((size_t)(r0 + 8) << 7) + col) = u;
                    *(unsigned*)(g_Az + (size_t)(r0 + 8) * KTOT + col) = u;
                }
            } else {
                if (r0 < nrows)
                    *(float2*)&out32[(size_t)r0 * DIM + col] = make_float2(v00, v01);
                if (r0 + 8 < nrows)
                    *(float2*)&out32[(size_t)(r0 + 8) * DIM + col] = make_float2(v10, v11);
            }
        }
    }
}

// ---------------------------------------------------------------------------
// Launch
// ---------------------------------------------------------------------------
extern "C" void kernel_launch(void* const* d_in, const int* in_sizes, int n_in,
                              void* d_out, int out_size)
{
    const float* x   = (const float*)d_in[0];
    const int*   ei  = (const int*)d_in[1];  // [2,E] int32
    const int*   et  = (const int*)d_in[2];  // [E]   int32
    const float* rw1 = (const float*)d_in[3];
    const float* ro1 = (const float*)d_in[4];
    const float* b1  = (const float*)d_in[5];
    const float* rw2 = (const float*)d_in[6];
    const float* ro2 = (const float*)d_in[7];
    const float* b2  = (const float*)d_in[8];
    float* out = (float*)d_out;

    const int n = in_sizes[0] / DIM;
    const int e = in_sizes[2];

    __half* wf;
    cudaGetSymbolAddress((void**)&wf, g_Wf);

    const int smem_bytes = 4 * 128 * AS2 * 2;   // 73728 (2-stage A+B)
    static bool attr_done = false;
    if (!attr_done) {
        cudaFuncSetAttribute(gemm_k_kernel,
                             cudaFuncAttributeMaxDynamicSharedMemorySize, smem_bytes);
        attr_done = true;
    }

    const int n8 = n * NREL;
    const int nscan = (n8 + 1023) / 1024;
    const int mtiles = (n + 127) / 128;
    const int nw = 9 * DIM * DIM;

    // conversions
    wconvert_kernel<<<(nw + 255) / 256, 256>>>(ro1, rw1, wf);
    wconvert_kernel<<<(nw + 255) / 256, 256>>>(ro2, rw2, wf + nw);
    convert_half_kernel<<<(n * 32 + 255) / 256, 256>>>(x, n * 32);

    // CSR build (shared by both layers)
    zero_cnt_kernel<<<(n8 / 4 + 255) / 256, 256>>>(n8 / 4);
    hist_kernel<<<(e + 255) / 256, 256>>>(ei, et, e);
    scan1_kernel<<<nscan, 256>>>(n8);
    scan2_kernel<<<1, 1024>>>(nscan);
    scan3_kernel<<<(n8 + 255) / 256, 256>>>(n8, e);
    sort_edges_kernel<<<(e + 255) / 256, 256>>>(ei, et, e);

    // layer 1: aggregate x into Z, then K=1152 GEMM -> fp16 activations
    aggz_kernel<<<(n * 32 + 255) / 256, 256>>>(n);
    gemm_k_kernel<<<mtiles, 256, smem_bytes>>>(wf, b1, nullptr, n, 0);

    // layer 2: aggregate h into Z, then GEMM -> fp32 out (relu fused)
    aggz_kernel<<<(n * 32 + 255) / 256, 256>>>(n);
    gemm_k_kernel<<<mtiles, 256, smem_bytes>>>(wf + nw, b2, out, n, 1);
}